// round 1
// baseline (speedup 1.0000x reference)
#include <cuda_runtime.h>
#include <math.h>

// Problem constants
#define NT   32
#define MB   8
#define KD   128
#define DD   384      // 3*K state dim
#define HH   128      // hidden
#define NXY  65536    // 256*256

// Scratch (device globals — no allocation allowed)
__device__ float g_W1T[DD * HH];   // W1T[i][j] = W1[j][i]   (i<384, j<128)
__device__ float g_W2T[HH * HH];   // W2T[i][j] = W2[j][i]
__device__ float g_W3T[HH * DD];   // W3T[j][o] = W3[o][j]   (j<128, o<384)
__device__ float g_coeff[NT * DD]; // coeff[t][d], d = k*3 + c

// ---------------------------------------------------------------------------
// Prep: transpose weights for coalesced access; seed coeff row 0 with init.
// ---------------------------------------------------------------------------
__global__ void prep_kernel(const float* __restrict__ W1,
                            const float* __restrict__ W2,
                            const float* __restrict__ W3,
                            const float* __restrict__ ic) {
    int g = blockIdx.x * blockDim.x + threadIdx.x;
    int stride = gridDim.x * blockDim.x;
    for (int idx = g; idx < DD * HH; idx += stride) {
        int i = idx >> 7, j = idx & 127;
        g_W1T[idx] = W1[j * DD + i];
    }
    for (int idx = g; idx < HH * HH; idx += stride) {
        int i = idx >> 7, j = idx & 127;
        g_W2T[idx] = W2[j * HH + i];
    }
    for (int idx = g; idx < HH * DD; idx += stride) {
        int j = idx / DD, o = idx - j * DD;
        g_W3T[idx] = W3[o * HH + j];
    }
    for (int idx = g; idx < DD; idx += stride) g_coeff[idx] = ic[idx];
}

// ---------------------------------------------------------------------------
// ODE: single CTA, 1024 threads. One trajectory (batch rows are identical).
// W1T cached in dynamic smem (192KB), W2 slice register-resident per thread,
// W3T streamed from L2 with coalesced loads.
// torchdiffeq fixed 'rk4' = 3/8 rule.
// ---------------------------------------------------------------------------
extern __shared__ float sW1T[];  // DD*HH floats

__global__ void __launch_bounds__(1024, 1)
ode_kernel(const float* __restrict__ t_arr,
           const float* __restrict__ b1,
           const float* __restrict__ b2,
           const float* __restrict__ b3) {
    __shared__ __align__(16) float y[DD];
    __shared__ __align__(16) float k1s[DD];
    __shared__ __align__(16) float k2s[DD];
    __shared__ __align__(16) float accv[DD];
    __shared__ __align__(16) float inb[DD];
    __shared__ __align__(16) float h1[HH];
    __shared__ __align__(16) float h2[HH];
    __shared__ __align__(16) float red[1024];
    __shared__ float st[NT];

    const int tid = threadIdx.x;
    const int r   = tid >> 7;        // 0..7  : reduction slice
    const int j   = tid & 127;       // 0..127: output index (layers 1/2)

    // stage W1T into smem
    for (int idx = tid; idx < DD * HH; idx += 1024) sW1T[idx] = g_W1T[idx];
    if (tid < NT) st[tid] = t_arr[tid];
    if (tid < DD) { float v = g_coeff[tid]; y[tid] = v; inb[tid] = v; }

    // W2 slice in registers: thread (r,j) owns W2[j][r*16 .. r*16+16)
    float w2r[16];
#pragma unroll
    for (int u = 0; u < 16; u++) w2r[u] = g_W2T[(r * 16 + u) * HH + j];

    const float rb1 = (tid < HH) ? b1[tid] : 0.f;
    const float rb2 = (tid < HH) ? b2[tid] : 0.f;
    const float rb3 = (tid < DD) ? b3[tid] : 0.f;

    // layer-3 mapping: threads 0..767 -> (rr in {0,1}, o in [0,384))
    const int o  = (tid < 384) ? tid : tid - 384;
    const int rr = (tid >= 384) ? 1 : 0;
    const int j0 = rr * 64;

    __syncthreads();

    for (int step = 0; step < NT - 1; step++) {
        const float dtv = st[step + 1] - st[step];
#pragma unroll 1
        for (int stage = 0; stage < 4; stage++) {
            // ---- layer 1: h1 = relu(W1 @ c + b1), partial over i-slice ----
            float a1 = 0.f;
            const int i0 = r * 48;
#pragma unroll
            for (int u = 0; u < 48; u += 4) {
                const float4 cv = *reinterpret_cast<const float4*>(&inb[i0 + u]);
                a1 = fmaf(sW1T[(i0 + u)     * HH + j], cv.x, a1);
                a1 = fmaf(sW1T[(i0 + u + 1) * HH + j], cv.y, a1);
                a1 = fmaf(sW1T[(i0 + u + 2) * HH + j], cv.z, a1);
                a1 = fmaf(sW1T[(i0 + u + 3) * HH + j], cv.w, a1);
            }
            red[tid] = a1;
            __syncthreads();
            if (tid < HH) {
                float s = rb1;
#pragma unroll
                for (int q = 0; q < 8; q++) s += red[q * 128 + tid];
                h1[tid] = fmaxf(s, 0.f);
            }
            __syncthreads();

            // ---- layer 2: h2 = elu(W2 @ h1 + b2), W2 in registers ----
            float a2 = 0.f;
            {
                const int ib = r * 16;
#pragma unroll
                for (int u = 0; u < 16; u += 4) {
                    const float4 hv = *reinterpret_cast<const float4*>(&h1[ib + u]);
                    a2 = fmaf(w2r[u],     hv.x, a2);
                    a2 = fmaf(w2r[u + 1], hv.y, a2);
                    a2 = fmaf(w2r[u + 2], hv.z, a2);
                    a2 = fmaf(w2r[u + 3], hv.w, a2);
                }
            }
            red[tid] = a2;
            __syncthreads();
            if (tid < HH) {
                float s = rb2;
#pragma unroll
                for (int q = 0; q < 8; q++) s += red[q * 128 + tid];
                h2[tid] = (s > 0.f) ? s : expm1f(s);
            }
            __syncthreads();

            // ---- layer 3: k = W3 @ h2 + b3, streamed coalesced from L2 ----
            if (tid < 768) {
                float a3 = 0.f;
#pragma unroll 8
                for (int u = 0; u < 64; u++) {
                    a3 = fmaf(g_W3T[(j0 + u) * DD + o], h2[j0 + u], a3);
                }
                red[tid] = a3;
            }
            __syncthreads();

            // ---- fold k into RK 3/8 state ----
            if (tid < DD) {
                const float kv = red[tid] + red[tid + 384] + rb3;
                if (stage == 0) {
                    k1s[tid] = kv; accv[tid] = kv;
                    inb[tid] = y[tid] + dtv * kv * (1.0f / 3.0f);
                } else if (stage == 1) {
                    k2s[tid] = kv; accv[tid] += 3.0f * kv;
                    inb[tid] = y[tid] + dtv * (kv - k1s[tid] * (1.0f / 3.0f));
                } else if (stage == 2) {
                    accv[tid] += 3.0f * kv;
                    inb[tid] = y[tid] + dtv * (k1s[tid] - k2s[tid] + kv);
                } else {
                    const float ny = y[tid] + dtv * (accv[tid] + kv) * 0.125f;
                    y[tid] = ny; inb[tid] = ny;
                    g_coeff[(step + 1) * DD + tid] = ny;
                }
            }
            __syncthreads();
        }
    }
}

// ---------------------------------------------------------------------------
// Einsum: soln[t,m,c,xy] = sum_k coeff[t,k,c] * basis[k,c,xy].
// Batch-independent -> compute once per (t,c,xy), write 8 m-copies.
// Block = 256 threads: 256 pixels x 32 t (thread: 4 pixels x 8 t).
// ---------------------------------------------------------------------------
__global__ void __launch_bounds__(256)
einsum_kernel(const float* __restrict__ basis, float* __restrict__ out) {
    const int c      = blockIdx.y;
    const int xy0    = blockIdx.x << 8;          // 256 px / block
    const int lane64 = threadIdx.x & 63;
    const int tg     = threadIdx.x >> 6;         // 0..3 -> t in [8tg, 8tg+8)
    const int t0     = tg * 8;
    const int pbase  = xy0 + lane64;

    float acc[8][4];
#pragma unroll
    for (int u = 0; u < 8; u++)
#pragma unroll
        for (int q = 0; q < 4; q++) acc[u][q] = 0.f;

#pragma unroll 4
    for (int k = 0; k < KD; k++) {
        const float* bk = basis + (((size_t)(k * 3 + c)) << 16) + pbase;
        const float bv0 = __ldg(bk);
        const float bv1 = __ldg(bk + 64);
        const float bv2 = __ldg(bk + 128);
        const float bv3 = __ldg(bk + 192);
        float av[8];
#pragma unroll
        for (int u = 0; u < 8; u++)
            av[u] = g_coeff[(t0 + u) * DD + k * 3 + c];   // warp-uniform broadcast
#pragma unroll
        for (int u = 0; u < 8; u++) {
            acc[u][0] = fmaf(av[u], bv0, acc[u][0]);
            acc[u][1] = fmaf(av[u], bv1, acc[u][1]);
            acc[u][2] = fmaf(av[u], bv2, acc[u][2]);
            acc[u][3] = fmaf(av[u], bv3, acc[u][3]);
        }
    }

#pragma unroll
    for (int u = 0; u < 8; u++) {
        const int t = t0 + u;
#pragma unroll
        for (int m = 0; m < MB; m++) {
            float* row = out + (((size_t)((t * MB + m) * 3 + c)) << 16) + pbase;
            row[0]   = acc[u][0];
            row[64]  = acc[u][1];
            row[128] = acc[u][2];
            row[192] = acc[u][3];
        }
    }
}

// ---------------------------------------------------------------------------
extern "C" void kernel_launch(void* const* d_in, const int* in_sizes, int n_in,
                              void* d_out, int out_size) {
    // inputs: 0 grid0 (unused), 1 t, 2 init_coeffs, 3 W1, 4 b1, 5 W2, 6 b2,
    //         7 W3, 8 b3, 9 basis
    const float* t_arr = (const float*)d_in[1];
    const float* ic    = (const float*)d_in[2];
    const float* W1    = (const float*)d_in[3];
    const float* b1    = (const float*)d_in[4];
    const float* W2    = (const float*)d_in[5];
    const float* b2    = (const float*)d_in[6];
    const float* W3    = (const float*)d_in[7];
    const float* b3    = (const float*)d_in[8];
    const float* basis = (const float*)d_in[9];
    float* out = (float*)d_out;

    cudaFuncSetAttribute(ode_kernel,
                         cudaFuncAttributeMaxDynamicSharedMemorySize,
                         DD * HH * (int)sizeof(float));

    prep_kernel<<<96, 256>>>(W1, W2, W3, ic);
    ode_kernel<<<1, 1024, DD * HH * sizeof(float)>>>(t_arr, b1, b2, b3);
    dim3 g(256, 3);
    einsum_kernel<<<g, 256>>>(basis, out);
}

// round 3
// speedup vs baseline: 1.6141x; 1.6141x over previous
#include <cuda_runtime.h>
#include <math.h>

// Problem constants
#define NT   32
#define MB   8
#define KD   128
#define DD   384      // 3*K state dim
#define HH   128      // hidden
#define NXY  65536    // 256*256

// Scratch (device globals — no allocation allowed)
__device__ float g_W1T[DD * HH];   // W1T[i][j] = W1[j][i]
__device__ float g_W2T[HH * HH];   // W2T[i][j] = W2[j][i]
__device__ float g_W3T[HH * DD];   // W3T[j][o] = W3[o][j]
__device__ float g_coeff[NT * DD]; // coeff[t][d], d = k*3 + c

// ---------------------------------------------------------------------------
// Prep: transpose weights; seed coeff row 0.
// ---------------------------------------------------------------------------
__global__ void prep_kernel(const float* __restrict__ W1,
                            const float* __restrict__ W2,
                            const float* __restrict__ W3,
                            const float* __restrict__ ic) {
    int g = blockIdx.x * blockDim.x + threadIdx.x;
    int stride = gridDim.x * blockDim.x;
    for (int idx = g; idx < DD * HH; idx += stride) {
        int i = idx >> 7, j = idx & 127;
        g_W1T[idx] = W1[j * DD + i];
    }
    for (int idx = g; idx < HH * HH; idx += stride) {
        int i = idx >> 7, j = idx & 127;
        g_W2T[idx] = W2[j * HH + i];
    }
    for (int idx = g; idx < HH * DD; idx += stride) {
        int j = idx / DD, o = idx - j * DD;
        g_W3T[idx] = W3[o * HH + j];
    }
    for (int idx = g; idx < DD; idx += stride) g_coeff[idx] = ic[idx];
}

// ---------------------------------------------------------------------------
// ODE: single CTA, 1024 threads, fully vectorized smem/L2 weight streaming.
//   layer1: warp w = i-slice [12w,12w+12), lane l = j-quad [4l,4l+4)
//           -> 12 LDS.128 per thread, full-row coalesced, conflict-free.
//   layer2: W2 slice register-resident (16 regs/thread).
//   layer3: 24 warps; warp w: j-slice sl=w/3 (16 j), lanes cover o-quads
//           -> 16 LDG.128 per thread from L2, coalesced.
// torchdiffeq fixed 'rk4' = 3/8 rule.
// ---------------------------------------------------------------------------
extern __shared__ float sW1T[];  // DD*HH floats = 192KB

__global__ void __launch_bounds__(1024, 1)
ode_kernel(const float* __restrict__ t_arr,
           const float* __restrict__ b1,
           const float* __restrict__ b2,
           const float* __restrict__ b3) {
    __shared__ __align__(16) float y[DD];
    __shared__ __align__(16) float k1s[DD];
    __shared__ __align__(16) float k2s[DD];
    __shared__ __align__(16) float accv[DD];
    __shared__ __align__(16) float inb[DD];
    __shared__ __align__(16) float h1[HH];
    __shared__ __align__(16) float h2[HH];
    __shared__ __align__(16) float red[4096];   // 16KB reduction scratch
    __shared__ float st[NT];

    const int tid = threadIdx.x;
    const int w   = tid >> 5;        // warp id 0..31
    const int l   = tid & 31;        // lane

    // stage W1T into smem (vectorized)
    {
        const float4* src = reinterpret_cast<const float4*>(g_W1T);
        float4* dst = reinterpret_cast<float4*>(sW1T);
        for (int idx = tid; idx < DD * HH / 4; idx += 1024) dst[idx] = src[idx];
    }
    if (tid < NT) st[tid] = t_arr[tid];
    if (tid < DD) { float v = g_coeff[tid]; y[tid] = v; inb[tid] = v; }

    // layer-2 weights: thread (r2,j2) owns W2[j2][16*r2 .. +16)
    const int r2 = tid >> 7;         // 0..7
    const int j2 = tid & 127;
    float w2r[16];
#pragma unroll
    for (int u = 0; u < 16; u++) w2r[u] = g_W2T[(r2 * 16 + u) * HH + j2];

    const float rb1 = (tid < HH) ? b1[tid] : 0.f;
    const float rb2 = (tid < HH) ? b2[tid] : 0.f;
    const float rb3 = (tid < DD) ? b3[tid] : 0.f;

    // layer-3 mapping: warps 0..23: sl = w/3 (j-slice), qo = (w%3)*32 + l
    const int sl = w / 3;            // 0..7 (valid for w<24)
    const int qo = (w - sl * 3) * 32 + l;  // 0..95
    const int o4 = qo * 4;           // output quad base

    __syncthreads();

    for (int step = 0; step < NT - 1; step++) {
        const float dtv = st[step + 1] - st[step];
#pragma unroll 1
        for (int stage = 0; stage < 4; stage++) {
            // ---- layer 1: warp w covers i in [12w,12w+12), lane l -> j-quad
            {
                float c[12];
                {
                    const float4* ib = reinterpret_cast<const float4*>(&inb[12 * w]);
                    float4 a = ib[0], bq = ib[1], cq = ib[2];
                    c[0]=a.x; c[1]=a.y; c[2]=a.z; c[3]=a.w;
                    c[4]=bq.x; c[5]=bq.y; c[6]=bq.z; c[7]=bq.w;
                    c[8]=cq.x; c[9]=cq.y; c[10]=cq.z; c[11]=cq.w;
                }
                float4 acc = make_float4(0.f, 0.f, 0.f, 0.f);
#pragma unroll
                for (int u = 0; u < 12; u++) {
                    const float4 wv = *reinterpret_cast<const float4*>(
                        &sW1T[(12 * w + u) * HH + 4 * l]);
                    acc.x = fmaf(wv.x, c[u], acc.x);
                    acc.y = fmaf(wv.y, c[u], acc.y);
                    acc.z = fmaf(wv.z, c[u], acc.z);
                    acc.w = fmaf(wv.w, c[u], acc.w);
                }
                // red[w*128 + 4l + e] = partial for output j=4l+e from slice w
                *reinterpret_cast<float4*>(&red[tid * 4]) = acc;
            }
            __syncthreads();

            // ---- layer1 reduce (threads 0..127): h1[j] = relu(sum + b1)
            if (tid < HH) {
                float s = rb1;
#pragma unroll
                for (int q = 0; q < 32; q++) s += red[q * 128 + tid];
                h1[tid] = fmaxf(s, 0.f);
            }
            __syncthreads();

            // ---- layer 2: register-resident W2, h1 slice via float4
            {
                float a2 = 0.f;
                const float4* hb = reinterpret_cast<const float4*>(&h1[r2 * 16]);
#pragma unroll
                for (int uu = 0; uu < 4; uu++) {
                    const float4 hv = hb[uu];
                    a2 = fmaf(w2r[uu * 4],     hv.x, a2);
                    a2 = fmaf(w2r[uu * 4 + 1], hv.y, a2);
                    a2 = fmaf(w2r[uu * 4 + 2], hv.z, a2);
                    a2 = fmaf(w2r[uu * 4 + 3], hv.w, a2);
                }
                red[tid] = a2;
            }
            __syncthreads();

            // ---- layer2 reduce: h2[j] = elu(sum + b2)
            if (tid < HH) {
                float s = rb2;
#pragma unroll
                for (int q = 0; q < 8; q++) s += red[q * 128 + tid];
                h2[tid] = (s > 0.f) ? s : expm1f(s);
            }
            __syncthreads();

            // ---- layer 3: warps 0..23, LDG.128 from L2, coalesced
            if (w < 24) {
                float hreg[16];
                {
                    const float4* hb = reinterpret_cast<const float4*>(&h2[16 * sl]);
#pragma unroll
                    for (int uu = 0; uu < 4; uu++) {
                        const float4 hv = hb[uu];
                        hreg[uu*4]=hv.x; hreg[uu*4+1]=hv.y;
                        hreg[uu*4+2]=hv.z; hreg[uu*4+3]=hv.w;
                    }
                }
                float4 acc = make_float4(0.f, 0.f, 0.f, 0.f);
#pragma unroll
                for (int u = 0; u < 16; u++) {
                    const float4 wv = __ldg(reinterpret_cast<const float4*>(
                        &g_W3T[(16 * sl + u) * DD + o4]));
                    acc.x = fmaf(wv.x, hreg[u], acc.x);
                    acc.y = fmaf(wv.y, hreg[u], acc.y);
                    acc.z = fmaf(wv.z, hreg[u], acc.z);
                    acc.w = fmaf(wv.w, hreg[u], acc.w);
                }
                // red[sl*384 + o]
                *reinterpret_cast<float4*>(&red[sl * DD + o4]) = acc;
            }
            __syncthreads();

            // ---- layer3 reduce + RK 3/8 fold (threads 0..383)
            if (tid < DD) {
                float kv = rb3;
#pragma unroll
                for (int q = 0; q < 8; q++) kv += red[q * DD + tid];
                if (stage == 0) {
                    k1s[tid] = kv; accv[tid] = kv;
                    inb[tid] = y[tid] + dtv * kv * (1.0f / 3.0f);
                } else if (stage == 1) {
                    k2s[tid] = kv; accv[tid] += 3.0f * kv;
                    inb[tid] = y[tid] + dtv * (kv - k1s[tid] * (1.0f / 3.0f));
                } else if (stage == 2) {
                    accv[tid] += 3.0f * kv;
                    inb[tid] = y[tid] + dtv * (k1s[tid] - k2s[tid] + kv);
                } else {
                    const float ny = y[tid] + dtv * (accv[tid] + kv) * 0.125f;
                    y[tid] = ny; inb[tid] = ny;
                    g_coeff[(step + 1) * DD + tid] = ny;
                }
            }
            __syncthreads();
        }
    }
}

// ---------------------------------------------------------------------------
// Einsum: soln[t,m,c,xy] = sum_k coeff[t,k,c] * basis[k,c,xy].
// Batch-independent -> compute once, write 8 m-copies.
// Block = 256 threads, covers 256 px (64 lanes x float4) x 32 t.
// coeff staged in smem (uniform LDS broadcasts); basis/out in float4.
// ---------------------------------------------------------------------------
__global__ void __launch_bounds__(256)
einsum_kernel(const float* __restrict__ basis, float* __restrict__ out) {
    __shared__ float sC[NT * KD];    // sC[t*128+k] = coeff[t][k*3+c], 16KB

    const int c      = blockIdx.y;
    const int xy0    = blockIdx.x << 8;          // 256 px / block
    const int lane64 = threadIdx.x & 63;
    const int tg     = threadIdx.x >> 6;         // 0..3
    const int t0     = tg * 8;
    const int pbase  = xy0 + lane64 * 4;

    for (int idx = threadIdx.x; idx < NT * KD; idx += 256) {
        int t = idx >> 7, k = idx & 127;
        sC[idx] = g_coeff[t * DD + k * 3 + c];
    }
    __syncthreads();

    float4 acc[8];
#pragma unroll
    for (int u = 0; u < 8; u++) acc[u] = make_float4(0.f, 0.f, 0.f, 0.f);

#pragma unroll 4
    for (int k = 0; k < KD; k++) {
        const float4 bv = __ldg(reinterpret_cast<const float4*>(
            basis + (((size_t)(k * 3 + c)) << 16) + pbase));
        float av[8];
#pragma unroll
        for (int u = 0; u < 8; u++) av[u] = sC[(t0 + u) * KD + k];
#pragma unroll
        for (int u = 0; u < 8; u++) {
            acc[u].x = fmaf(av[u], bv.x, acc[u].x);
            acc[u].y = fmaf(av[u], bv.y, acc[u].y);
            acc[u].z = fmaf(av[u], bv.z, acc[u].z);
            acc[u].w = fmaf(av[u], bv.w, acc[u].w);
        }
    }

#pragma unroll
    for (int u = 0; u < 8; u++) {
        const int t = t0 + u;
#pragma unroll
        for (int m = 0; m < MB; m++) {
            float4* row = reinterpret_cast<float4*>(
                out + (((size_t)((t * MB + m) * 3 + c)) << 16) + pbase);
            *row = acc[u];
        }
    }
}

// ---------------------------------------------------------------------------
extern "C" void kernel_launch(void* const* d_in, const int* in_sizes, int n_in,
                              void* d_out, int out_size) {
    // inputs: 0 grid0 (unused), 1 t, 2 init_coeffs, 3 W1, 4 b1, 5 W2, 6 b2,
    //         7 W3, 8 b3, 9 basis
    const float* t_arr = (const float*)d_in[1];
    const float* ic    = (const float*)d_in[2];
    const float* W1    = (const float*)d_in[3];
    const float* b1    = (const float*)d_in[4];
    const float* W2    = (const float*)d_in[5];
    const float* b2    = (const float*)d_in[6];
    const float* W3    = (const float*)d_in[7];
    const float* b3    = (const float*)d_in[8];
    const float* basis = (const float*)d_in[9];
    float* out = (float*)d_out;

    cudaFuncSetAttribute(ode_kernel,
                         cudaFuncAttributeMaxDynamicSharedMemorySize,
                         DD * HH * (int)sizeof(float));

    prep_kernel<<<96, 256>>>(W1, W2, W3, ic);
    ode_kernel<<<1, 1024, DD * HH * sizeof(float)>>>(t_arr, b1, b2, b3);
    dim3 g(256, 3);
    einsum_kernel<<<g, 256>>>(basis, out);
}